// round 15
// baseline (speedup 1.0000x reference)
#include <cuda_runtime.h>
#include <math.h>

#define NB 128      // batch
#define NS 512      // sequence length
#define NH 1024     // hidden dim
#define NE 128      // label embedding dim
#define NL 32       // num labels
#define G3 3072     // 3*NH
#define KH 1152     // NH + NE
#define NCTA 128    // persistent CTAs (1/SM, all co-resident in wave 1)

// ---------------- device scratch (static globals: allocation-free) ----------------
__device__ float g_xT[(size_t)NS * NH * NB];     // [s][k][b]
__device__ float g_gix[(size_t)NS * G3 * NB];    // [s][row][b] x-part of gi + b_ih
__device__ float g_hT[2][NH * NB];               // h state, [k][b], double buffered
__device__ float g_labT[2][NE * NB];             // label embedding, [e][b], double buffered
__device__ float g_woutT[NH * NL];               // [k][l]
__device__ volatile unsigned g_flags[NCTA];      // barrier epoch flags

typedef unsigned long long u64;

// ---------------- f32x2 helpers ----------------
__device__ __forceinline__ u64 pk2(float v) {
    u64 r; unsigned u = __float_as_uint(v);
    asm("mov.b64 %0, {%1, %2};" : "=l"(r) : "r"(u), "r"(u));
    return r;
}
__device__ __forceinline__ void fma2(u64 &d, u64 a, u64 b) {
    asm("fma.rn.f32x2 %0, %1, %2, %0;" : "+l"(d) : "l"(a), "l"(b));
}
__device__ __forceinline__ float2 upk(u64 v) {
    unsigned lo, hi;
    asm("mov.b64 {%0, %1}, %2;" : "=r"(lo), "=r"(hi) : "l"(v));
    return make_float2(__uint_as_float(lo), __uint_as_float(hi));
}

__device__ __forceinline__ float sigm(float x) { return 1.0f / (1.0f + expf(-x)); }
__device__ __forceinline__ float tanh_s(float x) {
    float ax = fabsf(x);
    float e  = expf(-2.0f * ax);
    float t  = (1.0f - e) / (1.0f + e);
    return (x < 0.0f) ? -t : t;
}

// ---------------- global barrier: flag array, all NCTA CTAs co-resident ----------------
__device__ __forceinline__ void gbar(int c, unsigned epoch) {
    __syncthreads();
    __threadfence();
    if (threadIdx.x == 0) g_flags[c] = epoch;
    if (threadIdx.x < NCTA) {
        while (g_flags[threadIdx.x] < epoch) { __nanosleep(32); }
    }
    __threadfence();
    __syncthreads();
}

// ---------------- kernel: transpose x[b][s][k] -> xT[s][k][b] ----------------
__global__ __launch_bounds__(256) void k_transpose(const float* __restrict__ x) {
    int s  = blockIdx.x;
    int k0 = blockIdx.y * 64;
    __shared__ float t[64][NB + 1];
    for (int i = threadIdx.x; i < 64 * NB; i += 256) {
        int b = i >> 6, kk = i & 63;
        t[kk][b] = x[((size_t)b * NS + s) * NH + k0 + kk];
    }
    __syncthreads();
    for (int i = threadIdx.x; i < 64 * NB; i += 256) {
        int kk = i >> 7, b = i & 127;
        g_xT[((size_t)s * NH + k0 + kk) * NB + b] = t[kk][b];
    }
}

// ---------------- kernel: init ----------------
__global__ void k_init(const float* __restrict__ emb, const float* __restrict__ Wout) {
    int tid = blockIdx.x * blockDim.x + threadIdx.x;
    int nt  = gridDim.x * blockDim.x;
    for (int i = tid; i < NH * NB; i += nt) g_hT[0][i] = 0.0f;
    for (int i = tid; i < NE * NB; i += nt) {
        int e = i >> 7, b = i & 127;
        g_labT[0][e * NB + b] = emb[e];          // emb[label id 0]
    }
    for (int i = tid; i < NH * NL; i += nt) {
        int k = i >> 5, l = i & 31;
        g_woutT[i] = Wout[(size_t)l * NH + k];
    }
    for (int i = tid; i < NCTA; i += nt) g_flags[i] = 0u;
}

// ---------------- kernel: phase A  gix[s][row][b] = W_ih[:, :1024] . x + b_ih ----------------
__global__ __launch_bounds__(256, 3) void k_gemm_a(const float* __restrict__ Wih,
                                                   const float* __restrict__ bih) {
    __shared__ u64 w2[48 * 128];   // 48 KB, weights duplicated into (w,w) pairs
    int s       = blockIdx.y;
    int rowbase = blockIdx.x * 48;
    int t  = threadIdx.x;
    int bp = t & 63, tr = t >> 6;

    u64 acc[12];
    #pragma unroll
    for (int i = 0; i < 12; i++) acc[i] = 0ull;

    const float* xs = g_xT + (size_t)s * NH * NB;

    for (int kt = 0; kt < 8; kt++) {
        int k0 = kt << 7;
        __syncthreads();
        for (int i = t; i < 48 * 32; i += 256) {
            int lr = i >> 5, kq = (i & 31) << 2;
            float4 v = *(const float4*)&Wih[(size_t)(rowbase + lr) * KH + k0 + kq];
            u64* dst = &w2[lr * 128 + kq];
            dst[0] = pk2(v.x); dst[1] = pk2(v.y); dst[2] = pk2(v.z); dst[3] = pk2(v.w);
        }
        __syncthreads();
        const u64* wb = &w2[(tr * 12) * 128];
        for (int kk = 0; kk < 128; kk += 2) {
            u64 x0 = *(const u64*)&xs[(size_t)(k0 + kk) * NB + 2 * bp];
            u64 x1 = *(const u64*)&xs[(size_t)(k0 + kk + 1) * NB + 2 * bp];
            #pragma unroll
            for (int rr = 0; rr < 12; rr++) {
                fma2(acc[rr], wb[rr * 128 + kk],     x0);
                fma2(acc[rr], wb[rr * 128 + kk + 1], x1);
            }
        }
    }

    float* go = g_gix + ((size_t)s * G3 + rowbase) * NB;
    #pragma unroll
    for (int rr = 0; rr < 12; rr++) {
        int lr = tr * 12 + rr;
        float2 v = upk(acc[rr]);
        float bias = bih[rowbase + lr];
        v.x += bias; v.y += bias;
        *(float2*)&go[(size_t)lr * NB + 2 * bp] = v;
    }
}

// ---------------- persistent sequential kernel ----------------
// 512 threads: t -> b = t&127, hh = (t>>7)&1 (k-half), rg = t>>8 (row group).
// Pairs p (adjacent output rows packed in one f32x2): rg0 -> p 0..5, rg1 -> p 6..11.
// p = g*4 + (jl>>1): g0=r (p0-3), g1=z (p4-7), g2=n (p8-11).
//
// smem layout (bytes):
//   [0,       98304)  wpair : u64[12][1024]  W_hh slice, row-pair interleaved
//   [98304,  110592)  lwpair: u64[12][128]   W_ih label-part slice, row-pair interleaved
//   [110592, 151552)  red: float2[4][128][10] (GRU partial exchange) | union lred float[32*17]
//   [151552, ...)     sb[24] bhh slice, sbo[32] bout, stot[32], spred
#define RED_OFF  110592
#define MISC_OFF 151552
#define SMEM_SEQ 152064

__global__ __launch_bounds__(512) void k_seq(
    const float* __restrict__ Whh, const float* __restrict__ Wih,
    const float* __restrict__ bhh, const float* __restrict__ emb,
    const float* __restrict__ bout, float* __restrict__ out)
{
    extern __shared__ char sm[];
    u64*    wpair  = (u64*)sm;
    u64*    lwpair = (u64*)(sm + 98304);
    float2* red    = (float2*)(sm + RED_OFF);
    float*  lred   = (float*)(sm + RED_OFF);
    float*  sb     = (float*)(sm + MISC_OFF);
    float*  sbo    = sb + 24;
    float*  stot   = sbo + 32;
    int*    spred  = (int*)(stot + 32);

    const int c  = blockIdx.x;
    const int t  = threadIdx.x;
    const int b  = t & 127;
    const int hh = (t >> 7) & 1;
    const int rg = t >> 8;
    const int rg6 = rg * 6;
    const int pp = t >> 7;        // gate-phase role: pair index 0..3 (with b)
    const int j0 = c * 8 + 2 * pp;

    // ---- one-time preload: W_hh slice (24 rows) as row-pair interleaved u32 ----
    unsigned* wp32 = (unsigned*)wpair;
    for (int idx = t; idx < 24 * 256; idx += 512) {
        int row = idx >> 8;            // 0..23
        int kq  = (idx & 255) << 2;    // 0..1020 step 4
        int g = row >> 3, jl = row & 7;
        int p = g * 4 + (jl >> 1), lane = jl & 1;
        float4 v = *(const float4*)&Whh[(size_t)(g * NH + c * 8 + jl) * NH + kq];
        wp32[((p * 1024 + kq + 0) << 1) + lane] = __float_as_uint(v.x);
        wp32[((p * 1024 + kq + 1) << 1) + lane] = __float_as_uint(v.y);
        wp32[((p * 1024 + kq + 2) << 1) + lane] = __float_as_uint(v.z);
        wp32[((p * 1024 + kq + 3) << 1) + lane] = __float_as_uint(v.w);
    }
    unsigned* lp32 = (unsigned*)lwpair;
    for (int idx = t; idx < 24 * 32; idx += 512) {
        int row = idx >> 5;
        int kq  = (idx & 31) << 2;
        int g = row >> 3, jl = row & 7;
        int p = g * 4 + (jl >> 1), lane = jl & 1;
        float4 v = *(const float4*)&Wih[(size_t)(g * NH + c * 8 + jl) * KH + NH + kq];
        lp32[((p * 128 + kq + 0) << 1) + lane] = __float_as_uint(v.x);
        lp32[((p * 128 + kq + 1) << 1) + lane] = __float_as_uint(v.y);
        lp32[((p * 128 + kq + 2) << 1) + lane] = __float_as_uint(v.z);
        lp32[((p * 128 + kq + 3) << 1) + lane] = __float_as_uint(v.w);
    }
    if (t < 24) sb[t]  = bhh[(t >> 3) * NH + c * 8 + (t & 7)];
    if (t < 32) sbo[t] = bout[t];
    __syncthreads();

    unsigned epoch = 0;
    for (int s = 0; s < NS; s++) {
        const float* hin  = g_hT[s & 1];
        const float* lin  = g_labT[s & 1];
        float*       hout = g_hT[(s + 1) & 1];
        float*       lout = g_labT[(s + 1) & 1];

        // ======== GRU: gh = h @ Whh.T  (quarter of work per thread) ========
        u64 acc[6], accLn[4];
        #pragma unroll
        for (int p = 0; p < 6; p++) acc[p] = 0ull;
        #pragma unroll
        for (int p = 0; p < 4; p++) accLn[p] = 0ull;

        const int kb = hh << 9;
        for (int k = kb; k < kb + 512; k += 8) {
            u64 hp[8];
            #pragma unroll
            for (int i = 0; i < 8; i++) hp[i] = pk2(__ldcg(&hin[(k + i) * NB + b]));
            #pragma unroll
            for (int g = 0; g < 4; g++) {
                #pragma unroll
                for (int p = 0; p < 6; p++) {
                    ulonglong2 w = *(const ulonglong2*)&wpair[(rg6 + p) * 1024 + k + 2 * g];
                    fma2(acc[p], w.x, hp[2 * g]);
                    fma2(acc[p], w.y, hp[2 * g + 1]);
                }
            }
        }

        // ---- prefetch gate-phase operands (DRAM gix + L2 hold), hidden by label loop ----
        const float* gixs = g_gix + (size_t)s * G3 * NB;
        float pg0 = __ldcg(&gixs[(size_t)(0 * NH + j0 + 0) * NB + b]);
        float pg1 = __ldcg(&gixs[(size_t)(0 * NH + j0 + 1) * NB + b]);
        float pg2 = __ldcg(&gixs[(size_t)(1 * NH + j0 + 0) * NB + b]);
        float pg3 = __ldcg(&gixs[(size_t)(1 * NH + j0 + 1) * NB + b]);
        float pg4 = __ldcg(&gixs[(size_t)(2 * NH + j0 + 0) * NB + b]);
        float pg5 = __ldcg(&gixs[(size_t)(2 * NH + j0 + 1) * NB + b]);
        float ho0 = __ldcg(&hin[(j0 + 0) * NB + b]);
        float ho1 = __ldcg(&hin[(j0 + 1) * NB + b]);

        // ---- label-embedding part: K = 128; r,z fold into acc; n-gate gi stays separate ----
        const int lb = hh << 6;
        if (rg == 0) {
            for (int k = lb; k < lb + 64; k += 4) {
                u64 lp[4];
                #pragma unroll
                for (int i = 0; i < 4; i++) lp[i] = pk2(__ldcg(&lin[(k + i) * NB + b]));
                #pragma unroll
                for (int g = 0; g < 2; g++) {
                    #pragma unroll
                    for (int p = 0; p < 6; p++) {
                        ulonglong2 w = *(const ulonglong2*)&lwpair[p * 128 + k + 2 * g];
                        fma2(acc[p], w.x, lp[2 * g]);
                        fma2(acc[p], w.y, lp[2 * g + 1]);
                    }
                }
            }
        } else {
            for (int k = lb; k < lb + 64; k += 4) {
                u64 lp[4];
                #pragma unroll
                for (int i = 0; i < 4; i++) lp[i] = pk2(__ldcg(&lin[(k + i) * NB + b]));
                #pragma unroll
                for (int g = 0; g < 2; g++) {
                    #pragma unroll
                    for (int p = 0; p < 2; p++) {            // p6,p7: z gate, fold
                        ulonglong2 w = *(const ulonglong2*)&lwpair[(6 + p) * 128 + k + 2 * g];
                        fma2(acc[p], w.x, lp[2 * g]);
                        fma2(acc[p], w.y, lp[2 * g + 1]);
                    }
                    #pragma unroll
                    for (int p = 0; p < 4; p++) {            // p8-11: n gate gi, separate
                        ulonglong2 w = *(const ulonglong2*)&lwpair[(8 + p) * 128 + k + 2 * g];
                        fma2(accLn[p], w.x, lp[2 * g]);
                        fma2(accLn[p], w.y, lp[2 * g + 1]);
                    }
                }
            }
        }

        // ---- exchange partials through smem ----
        {
            float2* myred = red + ((size_t)((hh * 2 + rg) * 128 + b)) * 10;
            #pragma unroll
            for (int p = 0; p < 6; p++) myred[p] = upk(acc[p]);
            #pragma unroll
            for (int p = 0; p < 4; p++) myred[6 + p] = upk(accLn[p]);
        }
        __syncthreads();

        // ---- gate math: thread (b, pp) computes jl = 2pp, 2pp+1 ----
        {
            #define RD2(rg_, slot_) make_float2( \
                red[((0 * 2 + (rg_)) * 128 + b) * 10 + (slot_)].x + red[((1 * 2 + (rg_)) * 128 + b) * 10 + (slot_)].x, \
                red[((0 * 2 + (rg_)) * 128 + b) * 10 + (slot_)].y + red[((1 * 2 + (rg_)) * 128 + b) * 10 + (slot_)].y)
            float2 rs = RD2(0, pp);
            float2 zs = (pp < 2) ? RD2(0, 4 + pp) : RD2(1, pp - 2);
            float2 ns = RD2(1, 2 + pp);
            float2 ls = RD2(1, 6 + pp);
            #undef RD2

            int jl = 2 * pp;
            float r0 = sigm(pg0 + rs.x + sb[jl]);
            float z0 = sigm(pg2 + zs.x + sb[8 + jl]);
            float n0 = tanh_s(pg4 + ls.x + r0 * (ns.x + sb[16 + jl]));
            hout[(j0 + 0) * NB + b] = (1.0f - z0) * n0 + z0 * ho0;

            float r1 = sigm(pg1 + rs.y + sb[jl + 1]);
            float z1 = sigm(pg3 + zs.y + sb[8 + jl + 1]);
            float n1 = tanh_s(pg5 + ls.y + r1 * (ns.y + sb[16 + jl + 1]));
            hout[(j0 + 1) * NB + b] = (1.0f - z1) * n1 + z1 * ho1;
        }
        epoch++; gbar(c, epoch);

        // ======== logits + argmax + label feedback (CTA c -> batch c) ========
        {
            int l   = t & 31;
            int seg = t >> 5;               // 0..15
            float part = 0.0f;
            const int kb2 = seg * 64;
            #pragma unroll 4
            for (int k = kb2; k < kb2 + 64; k++) {
                part = fmaf(__ldcg(&hout[k * NB + c]), __ldg(&g_woutT[k * NL + l]), part);
            }
            lred[l * 17 + seg] = part;
            __syncthreads();
            if (t < NL) {
                float sum = sbo[t];
                #pragma unroll
                for (int i = 0; i < 16; i++) sum += lred[t * 17 + i];
                stot[t] = sum;
                out[((size_t)c * NS + s) * NL + t] = sum;
            }
            __syncthreads();
            if (t == 0) {
                float best = stot[0]; int bi = 0;
                #pragma unroll
                for (int l2 = 1; l2 < NL; l2++)
                    if (stot[l2] > best) { best = stot[l2]; bi = l2; }  // first-max == jnp.argmax
                *spred = bi;
            }
            __syncthreads();
            if (t < NE) lout[t * NB + c] = __ldg(&emb[(*spred) * NE + t]);
        }
        epoch++; gbar(c, epoch);
    }
}

// ---------------- launch ----------------
extern "C" void kernel_launch(void* const* d_in, const int* in_sizes, int n_in,
                              void* d_out, int out_size) {
    (void)in_sizes; (void)n_in; (void)out_size;
    const float* x    = (const float*)d_in[0];
    const float* emb  = (const float*)d_in[1];
    const float* Wih  = (const float*)d_in[2];
    const float* Whh  = (const float*)d_in[3];
    const float* bih  = (const float*)d_in[4];
    const float* bhh  = (const float*)d_in[5];
    const float* Wout = (const float*)d_in[6];
    const float* bout = (const float*)d_in[7];
    float* out = (float*)d_out;

    static int smem_set = 0;
    if (!smem_set) {
        cudaFuncSetAttribute(k_seq, cudaFuncAttributeMaxDynamicSharedMemorySize, SMEM_SEQ);
        smem_set = 1;
    }

    k_transpose<<<dim3(NS, NH / 64), 256>>>(x);
    k_init<<<64, 256>>>(emb, Wout);
    k_gemm_a<<<dim3(G3 / 48, NS), 256>>>(Wih, bih);
    k_seq<<<NCTA, 512, SMEM_SEQ>>>(Whh, Wih, bhh, emb, bout, out);
}

// round 16
// speedup vs baseline: 1.0139x; 1.0139x over previous
#include <cuda_runtime.h>
#include <math.h>

#define NB 128      // batch
#define NS 512      // sequence length
#define NH 1024     // hidden dim
#define NE 128      // label embedding dim
#define NL 32       // num labels
#define G3 3072     // 3*NH
#define KH 1152     // NH + NE
#define NCTA 128    // persistent CTAs (1/SM, all co-resident in wave 1)

// ---------------- device scratch (static globals: allocation-free) ----------------
__device__ float g_xT[(size_t)NS * NH * NB];     // [s][k][b]
__device__ float g_gix[(size_t)NS * G3 * NB];    // [s][row][b] x-part of gi + b_ih
__device__ float g_hT[2][NH * NB];               // h state, [k][b], double buffered
__device__ float g_labT[2][NE * NB];             // label embedding, [e][b], double buffered
__device__ float g_woutT[NH * NL];               // [k][l]
__device__ volatile unsigned g_flags[NCTA];      // barrier epoch flags

typedef unsigned long long u64;

// ---------------- f32x2 helpers ----------------
__device__ __forceinline__ u64 pk2(float v) {
    u64 r; unsigned u = __float_as_uint(v);
    asm("mov.b64 %0, {%1, %2};" : "=l"(r) : "r"(u), "r"(u));
    return r;
}
__device__ __forceinline__ void fma2(u64 &d, u64 a, u64 b) {
    asm("fma.rn.f32x2 %0, %1, %2, %0;" : "+l"(d) : "l"(a), "l"(b));
}
__device__ __forceinline__ float2 upk(u64 v) {
    unsigned lo, hi;
    asm("mov.b64 {%0, %1}, %2;" : "=r"(lo), "=r"(hi) : "l"(v));
    return make_float2(__uint_as_float(lo), __uint_as_float(hi));
}

__device__ __forceinline__ float sigm(float x) { return 1.0f / (1.0f + expf(-x)); }
__device__ __forceinline__ float tanh_s(float x) {
    float ax = fabsf(x);
    float e  = expf(-2.0f * ax);
    float t  = (1.0f - e) / (1.0f + e);
    return (x < 0.0f) ? -t : t;
}

// ---------------- global barrier: flag array, all NCTA CTAs co-resident ----------------
__device__ __forceinline__ void gbar(int c, unsigned epoch) {
    __syncthreads();
    __threadfence();
    if (threadIdx.x == 0) g_flags[c] = epoch;
    if (threadIdx.x < NCTA) {
        while (g_flags[threadIdx.x] < epoch) { __nanosleep(32); }
    }
    __threadfence();
    __syncthreads();
}

// ---------------- kernel: transpose x[b][s][k] -> xT[s][k][b] ----------------
__global__ __launch_bounds__(256) void k_transpose(const float* __restrict__ x) {
    int s  = blockIdx.x;
    int k0 = blockIdx.y * 64;
    __shared__ float t[64][NB + 1];
    for (int i = threadIdx.x; i < 64 * NB; i += 256) {
        int b = i >> 6, kk = i & 63;
        t[kk][b] = x[((size_t)b * NS + s) * NH + k0 + kk];
    }
    __syncthreads();
    for (int i = threadIdx.x; i < 64 * NB; i += 256) {
        int kk = i >> 7, b = i & 127;
        g_xT[((size_t)s * NH + k0 + kk) * NB + b] = t[kk][b];
    }
}

// ---------------- kernel: init ----------------
__global__ void k_init(const float* __restrict__ emb, const float* __restrict__ Wout) {
    int tid = blockIdx.x * blockDim.x + threadIdx.x;
    int nt  = gridDim.x * blockDim.x;
    for (int i = tid; i < NH * NB; i += nt) g_hT[0][i] = 0.0f;
    for (int i = tid; i < NE * NB; i += nt) {
        int e = i >> 7, b = i & 127;
        g_labT[0][e * NB + b] = emb[e];          // emb[label id 0]
    }
    for (int i = tid; i < NH * NL; i += nt) {
        int k = i >> 5, l = i & 31;
        g_woutT[i] = Wout[(size_t)l * NH + k];
    }
    for (int i = tid; i < NCTA; i += nt) g_flags[i] = 0u;
}

// ---------------- kernel: phase A  gix[s][row][b] = W_ih[:, :1024] . x + b_ih ----------------
__global__ __launch_bounds__(256, 3) void k_gemm_a(const float* __restrict__ Wih,
                                                   const float* __restrict__ bih) {
    __shared__ u64 w2[48 * 128];   // 48 KB, weights duplicated into (w,w) pairs
    int s       = blockIdx.y;
    int rowbase = blockIdx.x * 48;
    int t  = threadIdx.x;
    int bp = t & 63, tr = t >> 6;

    u64 acc[12];
    #pragma unroll
    for (int i = 0; i < 12; i++) acc[i] = 0ull;

    const float* xs = g_xT + (size_t)s * NH * NB;

    for (int kt = 0; kt < 8; kt++) {
        int k0 = kt << 7;
        __syncthreads();
        for (int i = t; i < 48 * 32; i += 256) {
            int lr = i >> 5, kq = (i & 31) << 2;
            float4 v = *(const float4*)&Wih[(size_t)(rowbase + lr) * KH + k0 + kq];
            u64* dst = &w2[lr * 128 + kq];
            dst[0] = pk2(v.x); dst[1] = pk2(v.y); dst[2] = pk2(v.z); dst[3] = pk2(v.w);
        }
        __syncthreads();
        const u64* wb = &w2[(tr * 12) * 128];
        for (int kk = 0; kk < 128; kk += 2) {
            u64 x0 = *(const u64*)&xs[(size_t)(k0 + kk) * NB + 2 * bp];
            u64 x1 = *(const u64*)&xs[(size_t)(k0 + kk + 1) * NB + 2 * bp];
            #pragma unroll
            for (int rr = 0; rr < 12; rr++) {
                fma2(acc[rr], wb[rr * 128 + kk],     x0);
                fma2(acc[rr], wb[rr * 128 + kk + 1], x1);
            }
        }
    }

    float* go = g_gix + ((size_t)s * G3 + rowbase) * NB;
    #pragma unroll
    for (int rr = 0; rr < 12; rr++) {
        int lr = tr * 12 + rr;
        float2 v = upk(acc[rr]);
        float bias = bih[rowbase + lr];
        v.x += bias; v.y += bias;
        *(float2*)&go[(size_t)lr * NB + 2 * bp] = v;
    }
}

// ---------------- persistent sequential kernel ----------------
// 512 threads: t -> b = t&127, hh = (t>>7)&1 (k-half), rg = t>>8 (row group).
// Pairs p (adjacent output rows packed in one f32x2): rg0 -> p 0..5, rg1 -> p 6..11.
// p = g*4 + (jl>>1): g0=r (p0-3), g1=z (p4-7), g2=n (p8-11).
//
// smem layout (bytes):
//   [0,       98304)  wpair : u64[12][1024]  W_hh slice, row-pair interleaved
//   [98304,  110592)  lwpair: u64[12][128]   W_ih label-part slice, row-pair interleaved
//   [110592, 151552)  red: float2[4][128][10] (GRU partial exchange) | union lred float[32*17]
//   [151552, ...)     sb[24] bhh slice, sbo[32] bout, stot[32], spred
#define RED_OFF  110592
#define MISC_OFF 151552
#define SMEM_SEQ 152064

__global__ __launch_bounds__(512) void k_seq(
    const float* __restrict__ Whh, const float* __restrict__ Wih,
    const float* __restrict__ bhh, const float* __restrict__ emb,
    const float* __restrict__ bout, float* __restrict__ out)
{
    extern __shared__ char sm[];
    u64*    wpair  = (u64*)sm;
    u64*    lwpair = (u64*)(sm + 98304);
    float2* red    = (float2*)(sm + RED_OFF);
    float*  lred   = (float*)(sm + RED_OFF);
    float*  sb     = (float*)(sm + MISC_OFF);
    float*  sbo    = sb + 24;
    float*  stot   = sbo + 32;
    int*    spred  = (int*)(stot + 32);

    const int c  = blockIdx.x;
    const int t  = threadIdx.x;
    const int b  = t & 127;
    const int hh = (t >> 7) & 1;
    const int rg = t >> 8;
    const int rg6 = rg * 6;
    const int pp = t >> 7;        // gate-phase role: pair index 0..3 (with b)
    const int j0 = c * 8 + 2 * pp;

    // ---- one-time preload: W_hh slice (24 rows) as row-pair interleaved u32 ----
    unsigned* wp32 = (unsigned*)wpair;
    for (int idx = t; idx < 24 * 256; idx += 512) {
        int row = idx >> 8;            // 0..23
        int kq  = (idx & 255) << 2;    // 0..1020 step 4
        int g = row >> 3, jl = row & 7;
        int p = g * 4 + (jl >> 1), lane = jl & 1;
        float4 v = *(const float4*)&Whh[(size_t)(g * NH + c * 8 + jl) * NH + kq];
        wp32[((p * 1024 + kq + 0) << 1) + lane] = __float_as_uint(v.x);
        wp32[((p * 1024 + kq + 1) << 1) + lane] = __float_as_uint(v.y);
        wp32[((p * 1024 + kq + 2) << 1) + lane] = __float_as_uint(v.z);
        wp32[((p * 1024 + kq + 3) << 1) + lane] = __float_as_uint(v.w);
    }
    unsigned* lp32 = (unsigned*)lwpair;
    for (int idx = t; idx < 24 * 32; idx += 512) {
        int row = idx >> 5;
        int kq  = (idx & 31) << 2;
        int g = row >> 3, jl = row & 7;
        int p = g * 4 + (jl >> 1), lane = jl & 1;
        float4 v = *(const float4*)&Wih[(size_t)(g * NH + c * 8 + jl) * KH + NH + kq];
        lp32[((p * 128 + kq + 0) << 1) + lane] = __float_as_uint(v.x);
        lp32[((p * 128 + kq + 1) << 1) + lane] = __float_as_uint(v.y);
        lp32[((p * 128 + kq + 2) << 1) + lane] = __float_as_uint(v.z);
        lp32[((p * 128 + kq + 3) << 1) + lane] = __float_as_uint(v.w);
    }
    if (t < 24) sb[t]  = bhh[(t >> 3) * NH + c * 8 + (t & 7)];
    if (t < 32) sbo[t] = bout[t];
    __syncthreads();

    unsigned epoch = 0;
    for (int s = 0; s < NS; s++) {
        const float* hin  = g_hT[s & 1];
        const float* lin  = g_labT[s & 1];
        float*       hout = g_hT[(s + 1) & 1];
        float*       lout = g_labT[(s + 1) & 1];

        // ======== GRU: gh = h @ Whh.T  (quarter of work per thread) ========
        u64 acc[6], accLn[4];
        #pragma unroll
        for (int p = 0; p < 6; p++) acc[p] = 0ull;
        #pragma unroll
        for (int p = 0; p < 4; p++) accLn[p] = 0ull;

        const int kb = hh << 9;
        for (int k = kb; k < kb + 512; k += 8) {
            u64 hp[8];
            #pragma unroll
            for (int i = 0; i < 8; i++) hp[i] = pk2(__ldcg(&hin[(k + i) * NB + b]));
            #pragma unroll
            for (int g = 0; g < 4; g++) {
                #pragma unroll
                for (int p = 0; p < 6; p++) {
                    ulonglong2 w = *(const ulonglong2*)&wpair[(rg6 + p) * 1024 + k + 2 * g];
                    fma2(acc[p], w.x, hp[2 * g]);
                    fma2(acc[p], w.y, hp[2 * g + 1]);
                }
            }
        }

        // ---- prefetch gate-phase operands (DRAM gix + L2 hold), hidden by label loop ----
        const float* gixs = g_gix + (size_t)s * G3 * NB;
        float pg0 = __ldcg(&gixs[(size_t)(0 * NH + j0 + 0) * NB + b]);
        float pg1 = __ldcg(&gixs[(size_t)(0 * NH + j0 + 1) * NB + b]);
        float pg2 = __ldcg(&gixs[(size_t)(1 * NH + j0 + 0) * NB + b]);
        float pg3 = __ldcg(&gixs[(size_t)(1 * NH + j0 + 1) * NB + b]);
        float pg4 = __ldcg(&gixs[(size_t)(2 * NH + j0 + 0) * NB + b]);
        float pg5 = __ldcg(&gixs[(size_t)(2 * NH + j0 + 1) * NB + b]);
        float ho0 = __ldcg(&hin[(j0 + 0) * NB + b]);
        float ho1 = __ldcg(&hin[(j0 + 1) * NB + b]);

        // ---- label-embedding part: K = 128; r,z fold into acc; n-gate gi stays separate ----
        const int lb = hh << 6;
        if (rg == 0) {
            for (int k = lb; k < lb + 64; k += 4) {
                u64 lp[4];
                #pragma unroll
                for (int i = 0; i < 4; i++) lp[i] = pk2(__ldcg(&lin[(k + i) * NB + b]));
                #pragma unroll
                for (int g = 0; g < 2; g++) {
                    #pragma unroll
                    for (int p = 0; p < 6; p++) {
                        ulonglong2 w = *(const ulonglong2*)&lwpair[p * 128 + k + 2 * g];
                        fma2(acc[p], w.x, lp[2 * g]);
                        fma2(acc[p], w.y, lp[2 * g + 1]);
                    }
                }
            }
        } else {
            for (int k = lb; k < lb + 64; k += 4) {
                u64 lp[4];
                #pragma unroll
                for (int i = 0; i < 4; i++) lp[i] = pk2(__ldcg(&lin[(k + i) * NB + b]));
                #pragma unroll
                for (int g = 0; g < 2; g++) {
                    #pragma unroll
                    for (int p = 0; p < 2; p++) {            // p6,p7: z gate, fold
                        ulonglong2 w = *(const ulonglong2*)&lwpair[(6 + p) * 128 + k + 2 * g];
                        fma2(acc[p], w.x, lp[2 * g]);
                        fma2(acc[p], w.y, lp[2 * g + 1]);
                    }
                    #pragma unroll
                    for (int p = 0; p < 4; p++) {            // p8-11: n gate gi, separate
                        ulonglong2 w = *(const ulonglong2*)&lwpair[(8 + p) * 128 + k + 2 * g];
                        fma2(accLn[p], w.x, lp[2 * g]);
                        fma2(accLn[p], w.y, lp[2 * g + 1]);
                    }
                }
            }
        }

        // ---- exchange partials through smem ----
        {
            float2* myred = red + ((size_t)((hh * 2 + rg) * 128 + b)) * 10;
            #pragma unroll
            for (int p = 0; p < 6; p++) myred[p] = upk(acc[p]);
            #pragma unroll
            for (int p = 0; p < 4; p++) myred[6 + p] = upk(accLn[p]);
        }
        __syncthreads();

        // ---- gate math: thread (b, pp) computes jl = 2pp, 2pp+1 ----
        {
            #define RD2(rg_, slot_) make_float2( \
                red[((0 * 2 + (rg_)) * 128 + b) * 10 + (slot_)].x + red[((1 * 2 + (rg_)) * 128 + b) * 10 + (slot_)].x, \
                red[((0 * 2 + (rg_)) * 128 + b) * 10 + (slot_)].y + red[((1 * 2 + (rg_)) * 128 + b) * 10 + (slot_)].y)
            float2 rs = RD2(0, pp);
            float2 zs = (pp < 2) ? RD2(0, 4 + pp) : RD2(1, pp - 2);
            float2 ns = RD2(1, 2 + pp);
            float2 ls = RD2(1, 6 + pp);
            #undef RD2

            int jl = 2 * pp;
            float r0 = sigm(pg0 + rs.x + sb[jl]);
            float z0 = sigm(pg2 + zs.x + sb[8 + jl]);
            float n0 = tanh_s(pg4 + ls.x + r0 * (ns.x + sb[16 + jl]));
            hout[(j0 + 0) * NB + b] = (1.0f - z0) * n0 + z0 * ho0;

            float r1 = sigm(pg1 + rs.y + sb[jl + 1]);
            float z1 = sigm(pg3 + zs.y + sb[8 + jl + 1]);
            float n1 = tanh_s(pg5 + ls.y + r1 * (ns.y + sb[16 + jl + 1]));
            hout[(j0 + 1) * NB + b] = (1.0f - z1) * n1 + z1 * ho1;
        }
        epoch++; gbar(c, epoch);

        // ======== logits + argmax + label feedback (CTA c -> batch c) ========
        {
            int l   = t & 31;
            int seg = t >> 5;               // 0..15
            float part = 0.0f;
            const int kb2 = seg * 64;
            #pragma unroll 4
            for (int k = kb2; k < kb2 + 64; k++) {
                part = fmaf(__ldcg(&hout[k * NB + c]), __ldg(&g_woutT[k * NL + l]), part);
            }
            lred[l * 17 + seg] = part;
            __syncthreads();
            if (t < NL) {
                float sum = sbo[t];
                #pragma unroll
                for (int i = 0; i < 16; i++) sum += lred[t * 17 + i];
                stot[t] = sum;
                out[((size_t)c * NS + s) * NL + t] = sum;
            }
            __syncthreads();
            if (t == 0) {
                float best = stot[0]; int bi = 0;
                #pragma unroll
                for (int l2 = 1; l2 < NL; l2++)
                    if (stot[l2] > best) { best = stot[l2]; bi = l2; }  // first-max == jnp.argmax
                *spred = bi;
            }
            __syncthreads();
            if (t < NE) lout[t * NB + c] = __ldg(&emb[(*spred) * NE + t]);
        }
        epoch++; gbar(c, epoch);
    }
}

// ---------------- launch ----------------
extern "C" void kernel_launch(void* const* d_in, const int* in_sizes, int n_in,
                              void* d_out, int out_size) {
    (void)in_sizes; (void)n_in; (void)out_size;
    const float* x    = (const float*)d_in[0];
    const float* emb  = (const float*)d_in[1];
    const float* Wih  = (const float*)d_in[2];
    const float* Whh  = (const float*)d_in[3];
    const float* bih  = (const float*)d_in[4];
    const float* bhh  = (const float*)d_in[5];
    const float* Wout = (const float*)d_in[6];
    const float* bout = (const float*)d_in[7];
    float* out = (float*)d_out;

    static int smem_set = 0;
    if (!smem_set) {
        cudaFuncSetAttribute(k_seq, cudaFuncAttributeMaxDynamicSharedMemorySize, SMEM_SEQ);
        smem_set = 1;
    }

    k_transpose<<<dim3(NS, NH / 64), 256>>>(x);
    k_init<<<64, 256>>>(emb, Wout);
    k_gemm_a<<<dim3(G3 / 48, NS), 256>>>(Wih, bih);
    k_seq<<<NCTA, 512, SMEM_SEQ>>>(Whh, Wih, bhh, emb, bout, out);
}

// round 17
// speedup vs baseline: 1.4602x; 1.4401x over previous
#include <cuda_runtime.h>
#include <math.h>

#define NB 128      // batch
#define NS 512      // sequence length
#define NH 1024     // hidden dim
#define NE 128      // label embedding dim
#define NL 32       // num labels
#define G3 3072     // 3*NH
#define KH 1152     // NH + NE
#define NCTA 128    // persistent CTAs (1/SM, all co-resident in wave 1)

// ---------------- device scratch (static globals: allocation-free) ----------------
__device__ float g_xT[(size_t)NS * NH * NB];     // [s][k][b]
__device__ float g_gix[(size_t)NS * G3 * NB];    // [s][row][b] x-part of gi + b_ih
__device__ float g_hT[2][NH * NB];               // h state, [k][b], double buffered
__device__ float g_labT[2][NE * NB];             // label embedding, [e][b], double buffered
__device__ float g_woutT[NH * NL];               // [k][l]
__device__ unsigned g_bar_cnt;
__device__ unsigned g_bar_gen;

typedef unsigned long long u64;

// ---------------- f32x2 helpers ----------------
__device__ __forceinline__ u64 pk2(float v) {
    u64 r; unsigned u = __float_as_uint(v);
    asm("mov.b64 %0, {%1, %2};" : "=l"(r) : "r"(u), "r"(u));
    return r;
}
__device__ __forceinline__ void fma2(u64 &d, u64 a, u64 b) {
    asm("fma.rn.f32x2 %0, %1, %2, %0;" : "+l"(d) : "l"(a), "l"(b));
}
__device__ __forceinline__ float2 upk(u64 v) {
    unsigned lo, hi;
    asm("mov.b64 {%0, %1}, %2;" : "=r"(lo), "=r"(hi) : "l"(v));
    return make_float2(__uint_as_float(lo), __uint_as_float(hi));
}

__device__ __forceinline__ float sigm(float x) { return 1.0f / (1.0f + expf(-x)); }
__device__ __forceinline__ float tanh_s(float x) {
    float ax = fabsf(x);
    float e  = expf(-2.0f * ax);
    float t  = (1.0f - e) / (1.0f + e);
    return (x < 0.0f) ? -t : t;
}

// ---------------- global barrier (atomic ticket; all NCTA CTAs co-resident) ----------------
__device__ __forceinline__ void gbar(unsigned epoch) {
    __syncthreads();
    if (threadIdx.x == 0) {
        __threadfence();
        unsigned a = atomicAdd(&g_bar_cnt, 1u) + 1u;
        if (a == (unsigned)NCTA * epoch) {
            atomicExch(&g_bar_gen, epoch);
        } else {
            volatile unsigned* gen = &g_bar_gen;
            while (*gen < epoch) { __nanosleep(64); }
        }
        __threadfence();
    }
    __syncthreads();
}

// ---------------- kernel: transpose x[b][s][k] -> xT[s][k][b] ----------------
__global__ __launch_bounds__(256) void k_transpose(const float* __restrict__ x) {
    int s  = blockIdx.x;
    int k0 = blockIdx.y * 64;
    __shared__ float t[64][NB + 1];
    for (int i = threadIdx.x; i < 64 * NB; i += 256) {
        int b = i >> 6, kk = i & 63;
        t[kk][b] = x[((size_t)b * NS + s) * NH + k0 + kk];
    }
    __syncthreads();
    for (int i = threadIdx.x; i < 64 * NB; i += 256) {
        int kk = i >> 7, b = i & 127;
        g_xT[((size_t)s * NH + k0 + kk) * NB + b] = t[kk][b];
    }
}

// ---------------- kernel: init ----------------
__global__ void k_init(const float* __restrict__ emb, const float* __restrict__ Wout) {
    int tid = blockIdx.x * blockDim.x + threadIdx.x;
    int nt  = gridDim.x * blockDim.x;
    for (int i = tid; i < NH * NB; i += nt) g_hT[0][i] = 0.0f;
    for (int i = tid; i < NE * NB; i += nt) {
        int e = i >> 7, b = i & 127;
        g_labT[0][e * NB + b] = emb[e];          // emb[label id 0]
    }
    for (int i = tid; i < NH * NL; i += nt) {
        int k = i >> 5, l = i & 31;
        g_woutT[i] = Wout[(size_t)l * NH + k];
    }
    if (tid == 0) { g_bar_cnt = 0u; g_bar_gen = 0u; }
}

// ---------------- kernel: phase A  gix[s][row][b] = W_ih[:, :1024] . x + b_ih ----------------
__global__ __launch_bounds__(256, 3) void k_gemm_a(const float* __restrict__ Wih,
                                                   const float* __restrict__ bih) {
    __shared__ u64 w2[48 * 128];   // 48 KB, weights duplicated into (w,w) pairs
    int s       = blockIdx.y;
    int rowbase = blockIdx.x * 48;
    int t  = threadIdx.x;
    int bp = t & 63, tr = t >> 6;

    u64 acc[12];
    #pragma unroll
    for (int i = 0; i < 12; i++) acc[i] = 0ull;

    const float* xs = g_xT + (size_t)s * NH * NB;

    for (int kt = 0; kt < 8; kt++) {
        int k0 = kt << 7;
        __syncthreads();
        for (int i = t; i < 48 * 32; i += 256) {
            int lr = i >> 5, kq = (i & 31) << 2;
            float4 v = *(const float4*)&Wih[(size_t)(rowbase + lr) * KH + k0 + kq];
            u64* dst = &w2[lr * 128 + kq];
            dst[0] = pk2(v.x); dst[1] = pk2(v.y); dst[2] = pk2(v.z); dst[3] = pk2(v.w);
        }
        __syncthreads();
        const u64* wb = &w2[(tr * 12) * 128];
        for (int kk = 0; kk < 128; kk += 2) {
            u64 x0 = *(const u64*)&xs[(size_t)(k0 + kk) * NB + 2 * bp];
            u64 x1 = *(const u64*)&xs[(size_t)(k0 + kk + 1) * NB + 2 * bp];
            #pragma unroll
            for (int rr = 0; rr < 12; rr++) {
                fma2(acc[rr], wb[rr * 128 + kk],     x0);
                fma2(acc[rr], wb[rr * 128 + kk + 1], x1);
            }
        }
    }

    float* go = g_gix + ((size_t)s * G3 + rowbase) * NB;
    #pragma unroll
    for (int rr = 0; rr < 12; rr++) {
        int lr = tr * 12 + rr;
        float2 v = upk(acc[rr]);
        float bias = bih[rowbase + lr];
        v.x += bias; v.y += bias;
        *(float2*)&go[(size_t)lr * NB + 2 * bp] = v;
    }
}

// ---------------- persistent sequential kernel ----------------
// 512 threads: bq = t&63 (batches 2bq, 2bq+1), grp = t>>6:
//   kh = grp&1 (k-half), pg = grp>>1 (pair group: pairs 3pg..3pg+2).
// Row pairs p = g*4 + (jl>>1): g0=r (p0-3), g1=z (p4-7), g2=n (p8-11).
// acc[pi][bi] = (row even, row odd) for pair 3pg+pi, batch 2bq+bi.
// accL = same for label-K contribution (folded into acc at write for p<8;
// kept separate for n-gate pairs p>=8).
//
// smem layout (bytes):
//   [0,      98304)  wpair : u64[12][1024]  W_hh slice, row-pair interleaved
//   [98304, 110592)  lwpair: u64[12][128]   W_ih label-part slice
//   [110592,135168)  redM float2[2][12][128] | union lred float[32*17] (logits)
//   [135168,143360)  redL float2[2][4][128]
//   [143360, ...)    sb[24] bhh, sbo[32] bout, stot[32], spred
#define WP_OFF   0
#define LWP_OFF  98304
#define REDM_OFF 110592
#define REDL_OFF 135168
#define MISC_OFF 143360
#define SMEM_SEQ 143872

__global__ __launch_bounds__(512) void k_seq(
    const float* __restrict__ Whh, const float* __restrict__ Wih,
    const float* __restrict__ bhh, const float* __restrict__ emb,
    const float* __restrict__ bout, float* __restrict__ out)
{
    extern __shared__ char sm[];
    u64*    wpair  = (u64*)(sm + WP_OFF);
    u64*    lwpair = (u64*)(sm + LWP_OFF);
    float2* redM   = (float2*)(sm + REDM_OFF);
    float2* redL   = (float2*)(sm + REDL_OFF);
    float*  lred   = (float*)(sm + REDM_OFF);
    float*  sb     = (float*)(sm + MISC_OFF);
    float*  sbo    = sb + 24;
    float*  stot   = sbo + 32;
    int*    spred  = (int*)(stot + 32);

    const int c  = blockIdx.x;
    const int t  = threadIdx.x;
    const int bq = t & 63;
    const int grp = t >> 6;
    const int kh = grp & 1;
    const int pg = grp >> 1;       // 0..3
    const int p0 = pg * 3;         // first pair of this thread
    // gate-phase role
    const int b  = t & 127;
    const int pp = t >> 7;         // 0..3
    const int j0 = c * 8 + 2 * pp;

    // ---- one-time preload: W_hh slice (24 rows) as row-pair interleaved u32 ----
    unsigned* wp32 = (unsigned*)wpair;
    for (int idx = t; idx < 24 * 256; idx += 512) {
        int row = idx >> 8;            // 0..23
        int kq  = (idx & 255) << 2;    // 0..1020 step 4
        int g = row >> 3, jl = row & 7;
        int p = g * 4 + (jl >> 1), lane = jl & 1;
        float4 v = *(const float4*)&Whh[(size_t)(g * NH + c * 8 + jl) * NH + kq];
        wp32[((p * 1024 + kq + 0) << 1) + lane] = __float_as_uint(v.x);
        wp32[((p * 1024 + kq + 1) << 1) + lane] = __float_as_uint(v.y);
        wp32[((p * 1024 + kq + 2) << 1) + lane] = __float_as_uint(v.z);
        wp32[((p * 1024 + kq + 3) << 1) + lane] = __float_as_uint(v.w);
    }
    unsigned* lp32 = (unsigned*)lwpair;
    for (int idx = t; idx < 24 * 32; idx += 512) {
        int row = idx >> 5;
        int kq  = (idx & 31) << 2;
        int g = row >> 3, jl = row & 7;
        int p = g * 4 + (jl >> 1), lane = jl & 1;
        float4 v = *(const float4*)&Wih[(size_t)(g * NH + c * 8 + jl) * KH + NH + kq];
        lp32[((p * 128 + kq + 0) << 1) + lane] = __float_as_uint(v.x);
        lp32[((p * 128 + kq + 1) << 1) + lane] = __float_as_uint(v.y);
        lp32[((p * 128 + kq + 2) << 1) + lane] = __float_as_uint(v.z);
        lp32[((p * 128 + kq + 3) << 1) + lane] = __float_as_uint(v.w);
    }
    if (t < 24) sb[t]  = bhh[(t >> 3) * NH + c * 8 + (t & 7)];
    if (t < 32) sbo[t] = bout[t];
    __syncthreads();

    unsigned epoch = 0;
    for (int s = 0; s < NS; s++) {
        const float* hin  = g_hT[s & 1];
        const float* lin  = g_labT[s & 1];
        float*       hout = g_hT[(s + 1) & 1];
        float*       lout = g_labT[(s + 1) & 1];
        const float2* hin2 = (const float2*)hin;
        const float2* lin2 = (const float2*)lin;

        // ======== GRU: gh = h @ Whh.T  (3 pairs x 2 batches per thread) ========
        u64 acc[3][2], accL[3][2];
        #pragma unroll
        for (int i = 0; i < 3; i++) { acc[i][0] = acc[i][1] = 0ull; accL[i][0] = accL[i][1] = 0ull; }

        const int kb = kh << 9;
        for (int k = kb; k < kb + 512; k += 8) {
            float2 h2[8];
            #pragma unroll
            for (int i = 0; i < 8; i++) h2[i] = __ldcg(&hin2[(k + i) * 64 + bq]);
            #pragma unroll
            for (int i = 0; i < 8; i += 2) {
                u64 a0 = pk2(h2[i].x),     b0 = pk2(h2[i].y);
                u64 a1 = pk2(h2[i + 1].x), b1 = pk2(h2[i + 1].y);
                #pragma unroll
                for (int pi = 0; pi < 3; pi++) {
                    ulonglong2 w = *(const ulonglong2*)&wpair[(p0 + pi) * 1024 + k + i];
                    fma2(acc[pi][0], w.x, a0);
                    fma2(acc[pi][1], w.x, b0);
                    fma2(acc[pi][0], w.y, a1);
                    fma2(acc[pi][1], w.y, b1);
                }
            }
        }

        // ---- prefetch gate-phase operands (DRAM gix + L2 hold), hidden by label loop ----
        const float* gixs = g_gix + (size_t)s * G3 * NB;
        float pg0 = __ldcg(&gixs[(size_t)(0 * NH + j0 + 0) * NB + b]);
        float pg1 = __ldcg(&gixs[(size_t)(0 * NH + j0 + 1) * NB + b]);
        float pg2 = __ldcg(&gixs[(size_t)(1 * NH + j0 + 0) * NB + b]);
        float pg3 = __ldcg(&gixs[(size_t)(1 * NH + j0 + 1) * NB + b]);
        float pg4 = __ldcg(&gixs[(size_t)(2 * NH + j0 + 0) * NB + b]);
        float pg5 = __ldcg(&gixs[(size_t)(2 * NH + j0 + 1) * NB + b]);
        float ho0 = __ldcg(&hin[(j0 + 0) * NB + b]);
        float ho1 = __ldcg(&hin[(j0 + 1) * NB + b]);

        // ---- label-embedding part: K = 128 (this thread's half = 64) ----
        const int lb = kh << 6;
        for (int k = lb; k < lb + 64; k += 4) {
            float2 l2[4];
            #pragma unroll
            for (int i = 0; i < 4; i++) l2[i] = __ldcg(&lin2[(k + i) * 64 + bq]);
            #pragma unroll
            for (int i = 0; i < 4; i += 2) {
                u64 a0 = pk2(l2[i].x),     b0 = pk2(l2[i].y);
                u64 a1 = pk2(l2[i + 1].x), b1 = pk2(l2[i + 1].y);
                #pragma unroll
                for (int pi = 0; pi < 3; pi++) {
                    ulonglong2 w = *(const ulonglong2*)&lwpair[(p0 + pi) * 128 + k + i];
                    fma2(accL[pi][0], w.x, a0);
                    fma2(accL[pi][1], w.x, b0);
                    fma2(accL[pi][0], w.y, a1);
                    fma2(accL[pi][1], w.y, b1);
                }
            }
        }

        // ---- write partials: fold label into r/z pairs; keep separate for n pairs ----
        #pragma unroll
        for (int pi = 0; pi < 3; pi++) {
            int p = p0 + pi;
            #pragma unroll
            for (int bi = 0; bi < 2; bi++) {
                int bb = 2 * bq + bi;
                float2 m = upk(acc[pi][bi]);
                float2 l = upk(accL[pi][bi]);
                if (p < 8) {
                    m.x += l.x; m.y += l.y;
                    redM[(kh * 12 + p) * 128 + bb] = m;
                } else {
                    redM[(kh * 12 + p) * 128 + bb] = m;
                    redL[(kh * 4 + (p - 8)) * 128 + bb] = l;
                }
            }
        }
        __syncthreads();

        // ---- gate math: thread (b, pp) computes rows j0, j0+1 ----
        {
            #define RS(p_) make_float2( \
                redM[(0 * 12 + (p_)) * 128 + b].x + redM[(1 * 12 + (p_)) * 128 + b].x, \
                redM[(0 * 12 + (p_)) * 128 + b].y + redM[(1 * 12 + (p_)) * 128 + b].y)
            float2 rs = RS(pp);
            float2 zs = RS(4 + pp);
            float2 ns = RS(8 + pp);
            #undef RS
            float2 ls = make_float2(
                redL[(0 * 4 + pp) * 128 + b].x + redL[(1 * 4 + pp) * 128 + b].x,
                redL[(0 * 4 + pp) * 128 + b].y + redL[(1 * 4 + pp) * 128 + b].y);

            int jl = 2 * pp;
            float r0 = sigm(pg0 + rs.x + sb[jl]);
            float z0 = sigm(pg2 + zs.x + sb[8 + jl]);
            float n0 = tanh_s(pg4 + ls.x + r0 * (ns.x + sb[16 + jl]));
            hout[(j0 + 0) * NB + b] = (1.0f - z0) * n0 + z0 * ho0;

            float r1 = sigm(pg1 + rs.y + sb[jl + 1]);
            float z1 = sigm(pg3 + zs.y + sb[8 + jl + 1]);
            float n1 = tanh_s(pg5 + ls.y + r1 * (ns.y + sb[16 + jl + 1]));
            hout[(j0 + 1) * NB + b] = (1.0f - z1) * n1 + z1 * ho1;
        }
        epoch++; gbar(epoch);

        // ======== logits + argmax + label feedback (CTA c -> batch c) ========
        {
            int l   = t & 31;
            int seg = t >> 5;               // 0..15
            float part = 0.0f;
            const int kb2 = seg * 64;
            #pragma unroll 4
            for (int k = kb2; k < kb2 + 64; k++) {
                part = fmaf(__ldcg(&hout[k * NB + c]), __ldg(&g_woutT[k * NL + l]), part);
            }
            lred[l * 17 + seg] = part;
            __syncthreads();
            if (t < NL) {
                float sum = sbo[t];
                #pragma unroll
                for (int i = 0; i < 16; i++) sum += lred[t * 17 + i];
                stot[t] = sum;
                out[((size_t)c * NS + s) * NL + t] = sum;
            }
            __syncthreads();
            if (t == 0) {
                float best = stot[0]; int bi = 0;
                #pragma unroll
                for (int l2 = 1; l2 < NL; l2++)
                    if (stot[l2] > best) { best = stot[l2]; bi = l2; }  // first-max == jnp.argmax
                *spred = bi;
            }
            __syncthreads();
            if (t < NE) lout[t * NB + c] = __ldg(&emb[(*spred) * NE + t]);
        }
        epoch++; gbar(epoch);
    }
}

// ---------------- launch ----------------
extern "C" void kernel_launch(void* const* d_in, const int* in_sizes, int n_in,
                              void* d_out, int out_size) {
    (void)in_sizes; (void)n_in; (void)out_size;
    const float* x    = (const float*)d_in[0];
    const float* emb  = (const float*)d_in[1];
    const float* Wih  = (const float*)d_in[2];
    const float* Whh  = (const float*)d_in[3];
    const float* bih  = (const float*)d_in[4];
    const float* bhh  = (const float*)d_in[5];
    const float* Wout = (const float*)d_in[6];
    const float* bout = (const float*)d_in[7];
    float* out = (float*)d_out;

    static int smem_set = 0;
    if (!smem_set) {
        cudaFuncSetAttribute(k_seq, cudaFuncAttributeMaxDynamicSharedMemorySize, SMEM_SEQ);
        smem_set = 1;
    }

    k_transpose<<<dim3(NS, NH / 64), 256>>>(x);
    k_init<<<64, 256>>>(emb, Wout);
    k_gemm_a<<<dim3(G3 / 48, NS), 256>>>(Wih, bih);
    k_seq<<<NCTA, 512, SMEM_SEQ>>>(Whh, Wih, bhh, emb, bout, out);
}